// round 6
// baseline (speedup 1.0000x reference)
#include <cuda_runtime.h>
#include <cuda_fp16.h>

#define HD   128     // head dim
#define TOPK 64
#define SQL  1024
#define SKV  4096
#define NH   16
#define KV_ELEMS (NH * SKV * HD)   // 8,388,608 per tensor

// fp16 copies of K and V (16 MB each)
__device__ __half2 g_k16[KV_ELEMS / 2];
__device__ __half2 g_v16[KV_ELEMS / 2];

// ---- Pre-pass: fp32 -> fp16 conversion of K and V (8 elems/thread) ----
__global__ __launch_bounds__(256)
void convert_kv_kernel(const float4* __restrict__ k, const float4* __restrict__ v) {
    const int i = blockIdx.x * blockDim.x + threadIdx.x;  // over KV_ELEMS/8
    uint4* kd = reinterpret_cast<uint4*>(g_k16);
    uint4* vd = reinterpret_cast<uint4*>(g_v16);

    float4 a0 = k[2 * i], a1 = k[2 * i + 1];
    __half2 k0 = __floats2half2_rn(a0.x, a0.y);
    __half2 k1 = __floats2half2_rn(a0.z, a0.w);
    __half2 k2 = __floats2half2_rn(a1.x, a1.y);
    __half2 k3 = __floats2half2_rn(a1.z, a1.w);
    uint4 kp;
    kp.x = *reinterpret_cast<unsigned*>(&k0);
    kp.y = *reinterpret_cast<unsigned*>(&k1);
    kp.z = *reinterpret_cast<unsigned*>(&k2);
    kp.w = *reinterpret_cast<unsigned*>(&k3);
    kd[i] = kp;

    float4 b0 = v[2 * i], b1 = v[2 * i + 1];
    __half2 v0 = __floats2half2_rn(b0.x, b0.y);
    __half2 v1 = __floats2half2_rn(b0.z, b0.w);
    __half2 v2 = __floats2half2_rn(b1.x, b1.y);
    __half2 v3 = __floats2half2_rn(b1.z, b1.w);
    uint4 vp;
    vp.x = *reinterpret_cast<unsigned*>(&v0);
    vp.y = *reinterpret_cast<unsigned*>(&v1);
    vp.z = *reinterpret_cast<unsigned*>(&v2);
    vp.w = *reinterpret_cast<unsigned*>(&v3);
    vd[i] = vp;
}

// ---- Main sparse-attention kernel ----
// Block = (h, sq). 4 warps; warp w owns topk entries [w*16, w*16+16).
// Score phase: 8 lanes per row, 16 dims per lane (2x LDG.128); 4 rows in
// flight per group -> only 3 shfl + 1 STS per 4 rows.
// V phase: 16 lanes per row, 8 dims per lane (1x LDG.128), 2 rows per LDG.
__global__ __launch_bounds__(128)
void dsa_sparse_attn_kernel(const float* __restrict__ q,
                            const int*   __restrict__ topk_indices,
                            const float* __restrict__ topk_scores,
                            float* __restrict__ out) {
    const int sq   = blockIdx.x;
    const int h    = blockIdx.y;
    const int tid  = threadIdx.x;      // 0..127
    const int lane = tid & 31;
    const int warp = tid >> 5;

    __shared__ __align__(16) float q_s[HD];
    __shared__ __align__(16) int   idx_s[TOPK];
    __shared__ __align__(16) float sc_s[TOPK];
    __shared__ __align__(16) float w_s[TOPK];
    __shared__ __align__(16) float red_s[4][HD];

    // Stage q row and indices
    q_s[tid] = q[((size_t)h * SQL + sq) * HD + tid];
    if (tid < TOPK) {
        idx_s[tid] = topk_indices[(size_t)sq * TOPK + tid];
    }
    __syncthreads();

    const size_t hb   = (size_t)h * SKV * (HD / 2);  // head base, half2 units
    const int    base = warp * 16;

    // ---- Score phase ----
    {
        const int ssub = lane & 7;     // dim-slice within the 8-lane group
        const int rg   = lane >> 3;    // row-within-group (0..3)
        // q dims [ssub*16, ssub*16+16) in registers
        const float4* q4 = reinterpret_cast<const float4*>(q_s);
        const float4 qa = q4[ssub * 4 + 0];
        const float4 qb = q4[ssub * 4 + 1];
        const float4 qc = q4[ssub * 4 + 2];
        const float4 qd = q4[ssub * 4 + 3];

        #pragma unroll
        for (int g = 0; g < 4; g++) {
            const int t   = base + 4 * g + rg;
            const int row = idx_s[t];
            const uint4* kr = reinterpret_cast<const uint4*>(g_k16 + hb + (size_t)row * (HD / 2));
            uint4 r0 = kr[2 * ssub];
            uint4 r1 = kr[2 * ssub + 1];
            float2 f0 = __half22float2(*reinterpret_cast<__half2*>(&r0.x));
            float2 f1 = __half22float2(*reinterpret_cast<__half2*>(&r0.y));
            float2 f2 = __half22float2(*reinterpret_cast<__half2*>(&r0.z));
            float2 f3 = __half22float2(*reinterpret_cast<__half2*>(&r0.w));
            float2 f4 = __half22float2(*reinterpret_cast<__half2*>(&r1.x));
            float2 f5 = __half22float2(*reinterpret_cast<__half2*>(&r1.y));
            float2 f6 = __half22float2(*reinterpret_cast<__half2*>(&r1.z));
            float2 f7 = __half22float2(*reinterpret_cast<__half2*>(&r1.w));
            float p = qa.x * f0.x + qa.y * f0.y + qa.z * f1.x + qa.w * f1.y
                    + qb.x * f2.x + qb.y * f2.y + qb.z * f3.x + qb.w * f3.y
                    + qc.x * f4.x + qc.y * f4.y + qc.z * f5.x + qc.w * f5.y
                    + qd.x * f6.x + qd.y * f6.y + qd.z * f7.x + qd.w * f7.y;
            // reduce over the 8-lane group (all 4 rows in parallel)
            p += __shfl_xor_sync(0xffffffffu, p, 4);
            p += __shfl_xor_sync(0xffffffffu, p, 2);
            p += __shfl_xor_sync(0xffffffffu, p, 1);
            if (ssub == 0) sc_s[t] = p;
        }
    }
    __syncthreads();

    // ---- Softmax + score-weight fusion (warp 0) ----
    //   w_t = e_t * p_t / (sum(e*p) + 1e-12 * sum(e))
    if (warp == 0) {
        const float scale = 0.088388347648318447f;  // 128^-0.5
        float s0 = sc_s[lane]      * scale;
        float s1 = sc_s[lane + 32] * scale;
        float m = fmaxf(s0, s1);
        #pragma unroll
        for (int o = 16; o > 0; o >>= 1)
            m = fmaxf(m, __shfl_xor_sync(0xffffffffu, m, o));
        const float p0 = topk_scores[(size_t)sq * TOPK + lane];
        const float p1 = topk_scores[(size_t)sq * TOPK + lane + 32];
        const float e0 = __expf(s0 - m);
        const float e1 = __expf(s1 - m);
        const float w0 = e0 * p0;
        const float w1 = e1 * p1;
        float se = e0 + e1;
        float sw = w0 + w1;
        #pragma unroll
        for (int o = 16; o > 0; o >>= 1) {
            se += __shfl_xor_sync(0xffffffffu, se, o);
            sw += __shfl_xor_sync(0xffffffffu, sw, o);
        }
        const float inv = 1.0f / (sw + 1e-12f * se);
        w_s[lane]      = w0 * inv;
        w_s[lane + 32] = w1 * inv;
    }
    __syncthreads();

    // ---- V phase: 16 lanes per row, 8 dims per lane, 2 rows per LDG ----
    const int sub = lane & 15;
    const int hlf = lane >> 4;

    float a0 = 0.f, a1 = 0.f, a2 = 0.f, a3 = 0.f;
    float a4 = 0.f, a5 = 0.f, a6 = 0.f, a7 = 0.f;
    #pragma unroll
    for (int i = 0; i < 8; i++) {
        const int   t   = base + 2 * i + hlf;
        const int   row = idx_s[t];
        const float wgt = w_s[t];
        const uint4* vr = reinterpret_cast<const uint4*>(g_v16 + hb + (size_t)row * (HD / 2));
        uint4 raw = vr[sub];
        float2 f0 = __half22float2(*reinterpret_cast<__half2*>(&raw.x));
        float2 f1 = __half22float2(*reinterpret_cast<__half2*>(&raw.y));
        float2 f2 = __half22float2(*reinterpret_cast<__half2*>(&raw.z));
        float2 f3 = __half22float2(*reinterpret_cast<__half2*>(&raw.w));
        a0 += wgt * f0.x; a1 += wgt * f0.y;
        a2 += wgt * f1.x; a3 += wgt * f1.y;
        a4 += wgt * f2.x; a5 += wgt * f2.y;
        a6 += wgt * f3.x; a7 += wgt * f3.y;
    }
    // combine the two 16-lane halves (different rows, same dims)
    a0 += __shfl_xor_sync(0xffffffffu, a0, 16);
    a1 += __shfl_xor_sync(0xffffffffu, a1, 16);
    a2 += __shfl_xor_sync(0xffffffffu, a2, 16);
    a3 += __shfl_xor_sync(0xffffffffu, a3, 16);
    a4 += __shfl_xor_sync(0xffffffffu, a4, 16);
    a5 += __shfl_xor_sync(0xffffffffu, a5, 16);
    a6 += __shfl_xor_sync(0xffffffffu, a6, 16);
    a7 += __shfl_xor_sync(0xffffffffu, a7, 16);

    if (hlf == 0) {
        float4* r4 = reinterpret_cast<float4*>(&red_s[warp][sub * 8]);
        r4[0] = make_float4(a0, a1, a2, a3);
        r4[1] = make_float4(a4, a5, a6, a7);
    }
    __syncthreads();

    // cross-warp reduce + store (thread tid owns output dim tid)
    float r = (red_s[0][tid] + red_s[1][tid]) + (red_s[2][tid] + red_s[3][tid]);
    out[((size_t)h * SQL + sq) * HD + tid] = r;
}

extern "C" void kernel_launch(void* const* d_in, const int* in_sizes, int n_in,
                              void* d_out, int out_size) {
    const float* q   = (const float*)d_in[0];
    const float* k   = (const float*)d_in[1];
    const float* v   = (const float*)d_in[2];
    const int*   ti  = (const int*)  d_in[3];
    const float* ts  = (const float*)d_in[4];
    float* out = (float*)d_out;

    const int n8 = KV_ELEMS / 8;
    convert_kv_kernel<<<n8 / 256, 256>>>((const float4*)k, (const float4*)v);

    dim3 grid(SQL, NH);
    dsa_sparse_attn_kernel<<<grid, 128>>>(q, ti, ts, out);
}

// round 7
// speedup vs baseline: 1.2357x; 1.2357x over previous
#include <cuda_runtime.h>
#include <cuda_fp16.h>

#define HD   128     // head dim
#define TOPK 64
#define SQL  1024
#define SKV  4096
#define NH   16
#define KV_ELEMS (NH * SKV * HD)   // 8,388,608 per tensor

// fp16 copies of K and V (16 MB each)
__device__ __half2 g_k16[KV_ELEMS / 2];
__device__ __half2 g_v16[KV_ELEMS / 2];

// ---- Pre-pass: fp32 -> fp16 conversion of K and V (8 elems/thread) ----
__global__ __launch_bounds__(256)
void convert_kv_kernel(const float4* __restrict__ k, const float4* __restrict__ v) {
    const int i = blockIdx.x * blockDim.x + threadIdx.x;  // over KV_ELEMS/8
    uint4* kd = reinterpret_cast<uint4*>(g_k16);
    uint4* vd = reinterpret_cast<uint4*>(g_v16);

    float4 a0 = k[2 * i], a1 = k[2 * i + 1];
    __half2 k0 = __floats2half2_rn(a0.x, a0.y);
    __half2 k1 = __floats2half2_rn(a0.z, a0.w);
    __half2 k2 = __floats2half2_rn(a1.x, a1.y);
    __half2 k3 = __floats2half2_rn(a1.z, a1.w);
    uint4 kp;
    kp.x = *reinterpret_cast<unsigned*>(&k0);
    kp.y = *reinterpret_cast<unsigned*>(&k1);
    kp.z = *reinterpret_cast<unsigned*>(&k2);
    kp.w = *reinterpret_cast<unsigned*>(&k3);
    kd[i] = kp;

    float4 b0 = v[2 * i], b1 = v[2 * i + 1];
    __half2 v0 = __floats2half2_rn(b0.x, b0.y);
    __half2 v1 = __floats2half2_rn(b0.z, b0.w);
    __half2 v2 = __floats2half2_rn(b1.x, b1.y);
    __half2 v3 = __floats2half2_rn(b1.z, b1.w);
    uint4 vp;
    vp.x = *reinterpret_cast<unsigned*>(&v0);
    vp.y = *reinterpret_cast<unsigned*>(&v1);
    vp.z = *reinterpret_cast<unsigned*>(&v2);
    vp.w = *reinterpret_cast<unsigned*>(&v3);
    vd[i] = vp;
}

// ---- Main sparse-attention kernel ----
// Block = (h, sq). 4 warps; warp w owns topk entries [w*16, w*16+16).
// Lanes 0-15 process one row, lanes 16-31 a second row; each lane covers
// 8 head dims via one 16B load. Prefetched 2-deep.
__global__ __launch_bounds__(128, 12)
void dsa_sparse_attn_kernel(const float* __restrict__ q,
                            const int*   __restrict__ topk_indices,
                            const float* __restrict__ topk_scores,
                            float* __restrict__ out) {
    const int sq   = blockIdx.x;
    const int h    = blockIdx.y;
    const int tid  = threadIdx.x;      // 0..127
    const int lane = tid & 31;
    const int warp = tid >> 5;
    const int sub  = lane & 15;        // dim-group within the 16-lane half
    const int hlf  = lane >> 4;        // which row of the pair

    __shared__ __align__(16) float  q_s[HD];
    __shared__ __align__(16) int    idx_s[TOPK];
    __shared__ __align__(16) float2 sc_s[TOPK];   // even/odd-lane partial sums
    __shared__ __align__(16) float  w_s[TOPK];
    __shared__ __align__(16) float  red_s[4][HD];

    // Stage q row and indices
    q_s[tid] = q[((size_t)h * SQL + sq) * HD + tid];
    if (tid < TOPK) {
        idx_s[tid] = topk_indices[(size_t)sq * TOPK + tid];
    }
    __syncthreads();

    // q dims [sub*8, sub*8+8) in registers
    const float4* q4 = reinterpret_cast<const float4*>(q_s);
    const float4 qa = q4[sub * 2];
    const float4 qb = q4[sub * 2 + 1];

    const size_t hb   = (size_t)h * SKV * (HD / 2);  // head base, half2 units
    const int    base = warp * 16;

    // ---- Score phase: 8 iterations, 2 rows per iteration, 2-deep prefetch ----
    {
        uint4 raw;
        {
            const int row = idx_s[base + hlf];
            raw = reinterpret_cast<const uint4*>(g_k16 + hb + (size_t)row * (HD / 2))[sub];
        }
        #pragma unroll
        for (int i = 0; i < 8; i++) {
            uint4 rawn;
            if (i < 7) {
                const int rown = idx_s[base + 2 * (i + 1) + hlf];
                rawn = reinterpret_cast<const uint4*>(g_k16 + hb + (size_t)rown * (HD / 2))[sub];
            }
            float2 f0 = __half22float2(*reinterpret_cast<__half2*>(&raw.x));
            float2 f1 = __half22float2(*reinterpret_cast<__half2*>(&raw.y));
            float2 f2 = __half22float2(*reinterpret_cast<__half2*>(&raw.z));
            float2 f3 = __half22float2(*reinterpret_cast<__half2*>(&raw.w));
            float p = qa.x * f0.x + qa.y * f0.y + qa.z * f1.x + qa.w * f1.y
                    + qb.x * f2.x + qb.y * f2.y + qb.z * f3.x + qb.w * f3.y;
            // 3-shfl reduce: lane 0 = even-lane sum, lane 1 = odd-lane sum
            p += __shfl_xor_sync(0xffffffffu, p, 8);
            p += __shfl_xor_sync(0xffffffffu, p, 4);
            p += __shfl_xor_sync(0xffffffffu, p, 2);
            if (sub < 2) {
                float* dst = reinterpret_cast<float*>(&sc_s[base + 2 * i + hlf]);
                dst[sub] = p;
            }
            raw = rawn;
        }
    }
    __syncthreads();

    // ---- Softmax + score-weight fusion (warp 0) ----
    //   w_t = e_t * p_t / (sum(e*p) + 1e-12 * sum(e))
    if (warp == 0) {
        const float scale = 0.088388347648318447f;  // 128^-0.5
        const float2 v0 = sc_s[lane];
        const float2 v1 = sc_s[lane + 32];
        float s0 = (v0.x + v0.y) * scale;
        float s1 = (v1.x + v1.y) * scale;
        float m = fmaxf(s0, s1);
        #pragma unroll
        for (int o = 16; o > 0; o >>= 1)
            m = fmaxf(m, __shfl_xor_sync(0xffffffffu, m, o));
        const float p0 = topk_scores[(size_t)sq * TOPK + lane];
        const float p1 = topk_scores[(size_t)sq * TOPK + lane + 32];
        const float e0 = __expf(s0 - m);
        const float e1 = __expf(s1 - m);
        const float w0 = e0 * p0;
        const float w1 = e1 * p1;
        float se = e0 + e1;
        float sw = w0 + w1;
        #pragma unroll
        for (int o = 16; o > 0; o >>= 1) {
            se += __shfl_xor_sync(0xffffffffu, se, o);
            sw += __shfl_xor_sync(0xffffffffu, sw, o);
        }
        const float inv = 1.0f / (sw + 1e-12f * se);
        w_s[lane]      = w0 * inv;
        w_s[lane + 32] = w1 * inv;
    }
    __syncthreads();

    // ---- V phase: 2 rows per LDG, 8 dims per lane, 2-deep prefetch ----
    float a0 = 0.f, a1 = 0.f, a2 = 0.f, a3 = 0.f;
    float a4 = 0.f, a5 = 0.f, a6 = 0.f, a7 = 0.f;
    {
        uint4 raw;
        float wgt = w_s[base + hlf];
        {
            const int row = idx_s[base + hlf];
            raw = reinterpret_cast<const uint4*>(g_v16 + hb + (size_t)row * (HD / 2))[sub];
        }
        #pragma unroll
        for (int i = 0; i < 8; i++) {
            uint4 rawn;
            float wgtn;
            if (i < 7) {
                const int t = base + 2 * (i + 1) + hlf;
                const int rown = idx_s[t];
                wgtn = w_s[t];
                rawn = reinterpret_cast<const uint4*>(g_v16 + hb + (size_t)rown * (HD / 2))[sub];
            }
            float2 f0 = __half22float2(*reinterpret_cast<__half2*>(&raw.x));
            float2 f1 = __half22float2(*reinterpret_cast<__half2*>(&raw.y));
            float2 f2 = __half22float2(*reinterpret_cast<__half2*>(&raw.z));
            float2 f3 = __half22float2(*reinterpret_cast<__half2*>(&raw.w));
            a0 += wgt * f0.x; a1 += wgt * f0.y;
            a2 += wgt * f1.x; a3 += wgt * f1.y;
            a4 += wgt * f2.x; a5 += wgt * f2.y;
            a6 += wgt * f3.x; a7 += wgt * f3.y;
            raw = rawn;
            wgt = wgtn;
        }
    }
    // combine the two 16-lane halves (different rows, same dims)
    a0 += __shfl_xor_sync(0xffffffffu, a0, 16);
    a1 += __shfl_xor_sync(0xffffffffu, a1, 16);
    a2 += __shfl_xor_sync(0xffffffffu, a2, 16);
    a3 += __shfl_xor_sync(0xffffffffu, a3, 16);
    a4 += __shfl_xor_sync(0xffffffffu, a4, 16);
    a5 += __shfl_xor_sync(0xffffffffu, a5, 16);
    a6 += __shfl_xor_sync(0xffffffffu, a6, 16);
    a7 += __shfl_xor_sync(0xffffffffu, a7, 16);

    if (hlf == 0) {
        float4* r4 = reinterpret_cast<float4*>(&red_s[warp][sub * 8]);
        r4[0] = make_float4(a0, a1, a2, a3);
        r4[1] = make_float4(a4, a5, a6, a7);
    }
    __syncthreads();

    // cross-warp reduce + store (thread tid owns output dim tid)
    float r = (red_s[0][tid] + red_s[1][tid]) + (red_s[2][tid] + red_s[3][tid]);
    out[((size_t)h * SQL + sq) * HD + tid] = r;
}

extern "C" void kernel_launch(void* const* d_in, const int* in_sizes, int n_in,
                              void* d_out, int out_size) {
    const float* q   = (const float*)d_in[0];
    const float* k   = (const float*)d_in[1];
    const float* v   = (const float*)d_in[2];
    const int*   ti  = (const int*)  d_in[3];
    const float* ts  = (const float*)d_in[4];
    float* out = (float*)d_out;

    const int n8 = KV_ELEMS / 8;
    convert_kv_kernel<<<n8 / 256, 256>>>((const float4*)k, (const float4*)v);

    dim3 grid(SQL, NH);
    dsa_sparse_attn_kernel<<<grid, 128>>>(q, ti, ts, out);
}